// round 9
// baseline (speedup 1.0000x reference)
#include <cuda_runtime.h>
#include <cuda_bf16.h>
#include <math.h>
#include <stdint.h>

// Problem constants
#define CB 2
#define CT 2048
#define CD 2048
#define CN 16
#define CK 8
#define CH 128
#define CWIN 1024
#define CBT (CB*CT)

#define ROPE_QC (CB*CT*CN*64)
#define ROPE_KC (CB*CT*CK*64)

// Scratch (device globals; the exact 100.7MB set proven to pass the guard)
__device__ float g_q  [CBT*CN*CH];   // [B,T,N,H]
__device__ float g_k  [CBT*CK*CH];
__device__ float g_v  [CBT*CK*CH];
__device__ float g_enc[CBT*CN*CH];
__device__ float g_ts [64];

// ---------------------------------------------------------------------------
__global__ void rope_init_kernel() {
    int i = threadIdx.x;
    if (i < 64) g_ts[i] = (float)pow(10000.0, (double)i / 64.0);
}

__device__ __forceinline__ uint32_t pack_bf2(float x, float y) {
    __nv_bfloat162 h = __floats2bfloat162_rn(x, y);
    return *(uint32_t*)&h;
}

#define LDSM4(r, addr) \
    asm volatile("ldmatrix.sync.aligned.m8n8.x4.shared.b16 {%0,%1,%2,%3}, [%4];\n" \
        : "=r"((r)[0]), "=r"((r)[1]), "=r"((r)[2]), "=r"((r)[3]) : "r"(addr))
#define LDSM4T(r, addr) \
    asm volatile("ldmatrix.sync.aligned.m8n8.x4.trans.shared.b16 {%0,%1,%2,%3}, [%4];\n" \
        : "=r"((r)[0]), "=r"((r)[1]), "=r"((r)[2]), "=r"((r)[3]) : "r"(addr))
#define MMA16816(d, a, b) \
    asm volatile("mma.sync.aligned.m16n8k16.row.col.f32.bf16.bf16.f32 " \
        "{%0,%1,%2,%3}, {%4,%5,%6,%7}, {%8,%9}, {%0,%1,%2,%3};\n" \
        : "+f"((d)[0]), "+f"((d)[1]), "+f"((d)[2]), "+f"((d)[3]) \
        : "r"((a)[0]), "r"((a)[1]), "r"((a)[2]), "r"((a)[3]), "r"((b)[0]), "r"((b)[1]))

// ---------------------------------------------------------------------------
// Split-bf16 tensor-core GEMM, software-pipelined:
// one __syncthreads per BK=32 iter; split+STS of slice i+1 overlapped with
// mma of slice i; LDG prefetch distance 2 (two register sets).
// ---------------------------------------------------------------------------
#define A_STR 40
#define B_STR 136
#define A_TILE (128*A_STR)
#define B_TILE (32*B_STR)
#define GEM_SMEM ((4*A_TILE + 4*B_TILE) * 2)

__device__ __forceinline__ void gemm_split_128x128(
    const float* __restrict__ A, int lda,
    const float* __restrict__ B, int ldb,
    float* __restrict__ C, int ldc, int Kd)
{
    extern __shared__ __nv_bfloat16 smg[];
    __nv_bfloat16* const sA = smg;
    __nv_bfloat16* const sB = smg + 4 * A_TILE;
    const uint32_t sAb = (uint32_t)__cvta_generic_to_shared(sA);
    const uint32_t sBb = (uint32_t)__cvta_generic_to_shared(sB);

    const int tid  = threadIdx.x;
    const int lane = tid & 31;
    const int wid  = tid >> 5;
    const int wm   = wid >> 2;
    const int wn   = wid & 3;

    const int ar = tid >> 1, ac = (tid & 1) * 4;
    const int br = tid >> 3, bc = (tid & 7) * 4;

    const float* Ap = A + (size_t)ar * lda + ac;
    const float* Bp = B + (size_t)br * ldb + bc;

    float acc[4][4][4];
#pragma unroll
    for (int a = 0; a < 4; ++a)
#pragma unroll
        for (int b = 0; b < 4; ++b)
#pragma unroll
            for (int c = 0; c < 4; ++c) acc[a][b][c] = 0.f;

    float4 avA[4], bvA[4], avB[4], bvB[4];

    auto ldg = [&](int it, float4 (&av)[4], float4 (&bv)[4]) {
        const float* An = Ap + it * 32;
        const float* Bn = Bp + (size_t)it * 32 * ldb;
#pragma unroll
        for (int q = 0; q < 4; ++q) {
            av[q] = *(const float4*)(An + q * 8);
            bv[q] = *(const float4*)(Bn + q * 32);
        }
    };

    auto splitst = [&](int buf, const float4 (&av)[4], const float4 (&bv)[4]) {
        __nv_bfloat16* aHi = sA + (2 * buf)     * A_TILE;
        __nv_bfloat16* aLo = sA + (2 * buf + 1) * A_TILE;
        __nv_bfloat16* bHi = sB + (2 * buf)     * B_TILE;
        __nv_bfloat16* bLo = sB + (2 * buf + 1) * B_TILE;
#pragma unroll
        for (int q = 0; q < 4; ++q) {
            float a0 = av[q].x, a1 = av[q].y, a2 = av[q].z, a3 = av[q].w;
            float h0 = __bfloat162float(__float2bfloat16(a0));
            float h1 = __bfloat162float(__float2bfloat16(a1));
            float h2 = __bfloat162float(__float2bfloat16(a2));
            float h3 = __bfloat162float(__float2bfloat16(a3));
            uint2 H = make_uint2(pack_bf2(h0, h1), pack_bf2(h2, h3));
            uint2 L = make_uint2(pack_bf2(a0 - h0, a1 - h1), pack_bf2(a2 - h2, a3 - h3));
            *(uint2*)(aHi + ar * A_STR + ac + q * 8) = H;
            *(uint2*)(aLo + ar * A_STR + ac + q * 8) = L;

            float b0 = bv[q].x, b1 = bv[q].y, b2 = bv[q].z, b3 = bv[q].w;
            float g0 = __bfloat162float(__float2bfloat16(b0));
            float g1 = __bfloat162float(__float2bfloat16(b1));
            float g2 = __bfloat162float(__float2bfloat16(b2));
            float g3 = __bfloat162float(__float2bfloat16(b3));
            H = make_uint2(pack_bf2(g0, g1), pack_bf2(g2, g3));
            L = make_uint2(pack_bf2(b0 - g0, b1 - g1), pack_bf2(b2 - g2, b3 - g3));
            *(uint2*)(bHi + br * B_STR + bc + q * 32) = H;
            *(uint2*)(bLo + br * B_STR + bc + q * 32) = L;
        }
    };

    auto compute = [&](int ks, uint32_t aHiB, uint32_t aLoB,
                       uint32_t bHiB, uint32_t bLoB) {
        uint32_t bh4[2][4], bl4[2][4];
#pragma unroll
        for (int ntp = 0; ntp < 2; ++ntp) {
            uint32_t off = (ks*16 + (lane & 15)) * (B_STR * 2)
                         + (wn*32 + ntp*16 + (lane >> 4)*8) * 2;
            LDSM4T(bh4[ntp], bHiB + off);
            LDSM4T(bl4[ntp], bLoB + off);
        }
#pragma unroll
        for (int mt = 0; mt < 4; ++mt) {
            int row = wm * 64 + mt * 16 + (lane & 15);
            uint32_t off = row * (A_STR * 2) + ks*32 + (lane >> 4) * 16;
            uint32_t ahi[4], alo[4];
            LDSM4(ahi, aHiB + off);
            LDSM4(alo, aLoB + off);
#pragma unroll
            for (int ntp = 0; ntp < 2; ++ntp)
#pragma unroll
                for (int j = 0; j < 2; ++j) {
                    const int nt = ntp*2 + j;
                    MMA16816(acc[mt][nt], ahi, &bh4[ntp][2*j]);
                    MMA16816(acc[mt][nt], alo, &bh4[ntp][2*j]);
                    MMA16816(acc[mt][nt], ahi, &bl4[ntp][2*j]);
                }
        }
    };

    const int nIter = Kd >> 5;   // assumed >= 2 (Kd = 2048 here)
    ldg(0, avA, bvA);
    splitst(0, avA, bvA);
    ldg(1, avB, bvB);
    __syncthreads();

    for (int it = 0; it < nIter; ++it) {
        const int cur = it & 1;
        // prefetch slice it+2 into the register set consumed last iteration
        if ((it & 1) == 0) { if (it + 2 < nIter) ldg(it + 2, avA, bvA); }
        else               { if (it + 2 < nIter) ldg(it + 2, avB, bvB); }

        const uint32_t aHiB = sAb + (2 * cur)     * A_TILE * 2;
        const uint32_t aLoB = sAb + (2 * cur + 1) * A_TILE * 2;
        const uint32_t bHiB = sBb + (2 * cur)     * B_TILE * 2;
        const uint32_t bLoB = sBb + (2 * cur + 1) * B_TILE * 2;

        compute(0, aHiB, aLoB, bHiB, bLoB);

        // overlap: split slice it+1 into the other buffer while tensor pipe works
        if (it + 1 < nIter) {
            if ((it & 1) == 0) splitst(cur ^ 1, avB, bvB);
            else               splitst(cur ^ 1, avA, bvA);
        }

        compute(1, aHiB, aLoB, bHiB, bLoB);
        __syncthreads();
    }

    const int rg = lane >> 2, tg = lane & 3;
#pragma unroll
    for (int mt = 0; mt < 4; ++mt)
#pragma unroll
        for (int nt = 0; nt < 4; ++nt) {
            int r = wm * 64 + mt * 16 + rg;
            int c = wn * 32 + nt * 8 + tg * 2;
            *(float2*)&C[(size_t)r * ldc + c]       = make_float2(acc[mt][nt][0], acc[mt][nt][1]);
            *(float2*)&C[(size_t)(r + 8) * ldc + c] = make_float2(acc[mt][nt][2], acc[mt][nt][3]);
        }
}

// ---------------------------------------------------------------------------
__global__ __launch_bounds__(256, 1) void qkv_kernel(
    const float* __restrict__ x,
    const float* __restrict__ wq,
    const float* __restrict__ wkv)
{
    const int m0 = blockIdx.x * 128;
    const int h  = blockIdx.y;
    const float* A = x + (size_t)m0 * CD;
    const float* W;
    float* C; int ldc;
    if (h < CN) {
        W = wq + (size_t)h * CD * CH;
        C = g_q + (size_t)m0 * CN * CH + h * CH; ldc = CN * CH;
    } else if (h < CN + CK) {
        const int kk = h - CN;
        W = wkv + (size_t)kk * CD * CH;
        C = g_k + (size_t)m0 * CK * CH + kk * CH; ldc = CK * CH;
    } else {
        const int kk = h - CN - CK;
        W = wkv + (size_t)(CK + kk) * CD * CH;
        C = g_v + (size_t)m0 * CK * CH + kk * CH; ldc = CK * CH;
    }
    gemm_split_128x128(A, CD, W, CH, C, ldc, CD);
}

__global__ __launch_bounds__(256, 1) void oproj_kernel(
    const float* __restrict__ wo, float* __restrict__ out)
{
    const int m0 = blockIdx.x * 128;
    const int n0 = blockIdx.y * 128;
    gemm_split_128x128(g_enc + (size_t)m0 * (CN*CH), CN*CH,
                       wo + n0, CD,
                       out + (size_t)m0 * CD + n0, CD, CN*CH);
}

// ---------------------------------------------------------------------------
__global__ __launch_bounds__(256) void rope_kernel(const int* __restrict__ seg)
{
    int idx = blockIdx.x * blockDim.x + threadIdx.x;
    if (idx >= ROPE_QC + ROPE_KC) return;

    float* buf; int heads; float scal; int lidx;
    if (idx < ROPE_QC) {
        buf = g_q; heads = CN; scal = 0.08838834764831845f; lidx = idx;
    } else {
        buf = g_k; heads = CK; scal = 1.0f; lidx = idx - ROPE_QC;
    }
    const int i    = lidx & 63;
    const int rest = lidx >> 6;
    const int bt   = rest / heads;
    const int pos  = seg[bt];

    float ts = g_ts[i];
    float ang = (float)pos / ts;
    float s, c;
    sincosf(ang, &s, &c);

    float* p = buf + (size_t)rest * CH;
    float x1 = p[i];
    float x2 = p[i + 64];
    p[i]      = (x1 * c - x2 * s) * scal;
    p[i + 64] = (x2 * c + x1 * s) * scal;
}

// ---------------------------------------------------------------------------
__device__ __forceinline__ float softcap(float v)
{
    float x = v * (1.0f / 50.0f);
    float ax = fabsf(x);
    if (ax < 0.25f) {
        float x2 = x * x;
        float t = x * (1.0f + x2 * (-1.0f/3.0f + x2 * (2.0f/15.0f + x2 * (-17.0f/315.0f))));
        return t * 50.0f;
    }
    return tanhf(x) * 50.0f;
}

// ---------------------------------------------------------------------------
// Tensor-core flash attention: x4 ldmatrix for K/V, single barrier per step.
// grid (T/128, N, B), 256 threads.
// ---------------------------------------------------------------------------
#define AROW 272                        // bytes per smem row (128 bf16 + 8 pad)
#define QTILE (128*AROW)                // 34816
#define KTILE (64*AROW)                 // 17408
#define ASTG  (4*KTILE)                 // 69632 per KV stage
#define AKV0  (2*QTILE)                 // 69632
#define ATT_SMEM (AKV0 + 2*ASTG)        // 208896

__global__ __launch_bounds__(256, 1) void attn_kernel()
{
    extern __shared__ char sma[];
    const uint32_t sb = (uint32_t)__cvta_generic_to_shared(sma);

    const int tid = threadIdx.x, lane = tid & 31, w = tid >> 5;
    const int rg = lane >> 2, tg = lane & 3;
    const int qt = blockIdx.x, n = blockIdx.y, b = blockIdx.z;
    const int kk = n >> 1;
    const int q0 = qt * 128;
    const int row0 = w * 16;

    // ---- stage Q: fp32 -> hi/lo bf16 smem (4096 float4 items) ----
#pragma unroll
    for (int p = 0; p < 16; ++p) {
        int idx = tid + p * 256;
        int r = idx >> 5, c4 = idx & 31;
        float4 f = *(const float4*)(g_q +
            ((size_t)(b*CT + q0 + r) * CN + n) * CH + c4 * 4);
        float h0 = __bfloat162float(__float2bfloat16(f.x));
        float h1 = __bfloat162float(__float2bfloat16(f.y));
        float h2 = __bfloat162float(__float2bfloat16(f.z));
        float h3 = __bfloat162float(__float2bfloat16(f.w));
        uint32_t off = (uint32_t)(r * AROW + c4 * 8);
        *(uint2*)(sma + off)         = make_uint2(pack_bf2(h0, h1), pack_bf2(h2, h3));
        *(uint2*)(sma + QTILE + off) = make_uint2(pack_bf2(f.x - h0, f.y - h1),
                                                  pack_bf2(f.z - h2, f.w - h3));
    }

    int st0 = q0 - (CWIN - 1); if (st0 < 0) st0 = 0; st0 >>= 6;
    const int stL = (q0 + 127) >> 6;

    float4 kreg[8], vreg[8];
    const int sr = tid >> 5, sc = tid & 31;

    auto ldKV = [&](int st) {
        const int s0 = st * 64;
#pragma unroll
        for (int p = 0; p < 8; ++p) {
            int r = sr + p * 8;
            size_t off = ((size_t)(b*CT + s0 + r) * CK + kk) * CH + sc * 4;
            kreg[p] = *(const float4*)(g_k + off);
            vreg[p] = *(const float4*)(g_v + off);
        }
    };
    auto stKV = [&](int bsel) {
        const uint32_t kb = AKV0 + bsel * ASTG;
#pragma unroll
        for (int p = 0; p < 8; ++p) {
            int r = sr + p * 8;
            uint32_t off = (uint32_t)(r * AROW + sc * 8);
            float4 f = kreg[p];
            float h0 = __bfloat162float(__float2bfloat16(f.x));
            float h1 = __bfloat162float(__float2bfloat16(f.y));
            float h2 = __bfloat162float(__float2bfloat16(f.z));
            float h3 = __bfloat162float(__float2bfloat16(f.w));
            *(uint2*)(sma + kb + off) = make_uint2(pack_bf2(h0, h1), pack_bf2(h2, h3));
            *(uint2*)(sma + kb + KTILE + off) =
                make_uint2(pack_bf2(f.x - h0, f.y - h1), pack_bf2(f.z - h2, f.w - h3));
            f = vreg[p];
            h0 = __bfloat162float(__float2bfloat16(f.x));
            h1 = __bfloat162float(__float2bfloat16(f.y));
            h2 = __bfloat162float(__float2bfloat16(f.z));
            h3 = __bfloat162float(__float2bfloat16(f.w));
            *(uint2*)(sma + kb + 2*KTILE + off) = make_uint2(pack_bf2(h0, h1), pack_bf2(h2, h3));
            *(uint2*)(sma + kb + 3*KTILE + off) =
                make_uint2(pack_bf2(f.x - h0, f.y - h1), pack_bf2(f.z - h2, f.w - h3));
        }
    };

    ldKV(st0);
    stKV(0);
    if (st0 + 1 <= stL) ldKV(st0 + 1);
    __syncthreads();

    float m_i[2] = {-1e30f, -1e30f}, l_i[2] = {0.f, 0.f};
    float ao[16][4];
#pragma unroll
    for (int t = 0; t < 16; ++t)
#pragma unroll
        for (int c = 0; c < 4; ++c) ao[t][c] = 0.f;

    for (int st = st0; st <= stL; ++st) {
        const int bsel = (st - st0) & 1;
        const uint32_t kb  = sb + AKV0 + bsel * ASTG;
        const uint32_t vhB = kb + 2*KTILE;
        const int s0 = st * 64;

        // ---- S = Q K^T (3-pass split, x4 K loads) ----
        float as[8][4];
#pragma unroll
        for (int nt = 0; nt < 8; ++nt)
#pragma unroll
            for (int c = 0; c < 4; ++c) as[nt][c] = 0.f;

#pragma unroll
        for (int kc = 0; kc < 8; ++kc) {
            uint32_t qa = sb + (row0 + (lane & 15)) * AROW + kc*32 + (lane >> 4) * 16;
            uint32_t qh[4], ql[4];
            LDSM4(qh, qa);
            LDSM4(ql, qa + QTILE);
#pragma unroll
            for (int ntp = 0; ntp < 4; ++ntp) {
                uint32_t ka = kb + (ntp*16 + (lane >> 4)*8 + (lane & 7)) * AROW
                            + kc*32 + ((lane >> 3) & 1) * 16;
                uint32_t kh4[4], kl4[4];
                LDSM4(kh4, ka);
                LDSM4(kl4, ka + KTILE);
#pragma unroll
                for (int j = 0; j < 2; ++j) {
                    const int nt = ntp*2 + j;
                    MMA16816(as[nt], qh, &kh4[2*j]);
                    MMA16816(as[nt], ql, &kh4[2*j]);
                    MMA16816(as[nt], qh, &kl4[2*j]);
                }
            }
        }

        // ---- softcap + mask + online softmax ----
        float scale_[2];
#pragma unroll
        for (int hf = 0; hf < 2; ++hf) {
            const int qrow = q0 + row0 + rg + hf*8;
            float rm = -1e30f;
#pragma unroll
            for (int nt = 0; nt < 8; ++nt)
#pragma unroll
                for (int cc = 0; cc < 2; ++cc) {
                    const int scol = s0 + nt*8 + tg*2 + cc;
                    float xx = softcap(as[nt][hf*2 + cc]);
                    const bool valid = (scol <= qrow) && (qrow - scol < CWIN);
                    xx = valid ? xx : -1e30f;
                    as[nt][hf*2 + cc] = xx;
                    rm = fmaxf(rm, xx);
                }
            rm = fmaxf(rm, __shfl_xor_sync(0xffffffffu, rm, 1));
            rm = fmaxf(rm, __shfl_xor_sync(0xffffffffu, rm, 2));

            const float mn = fmaxf(m_i[hf], rm);
            scale_[hf] = __expf(m_i[hf] - mn);
            m_i[hf] = mn;

            float sl = 0.f;
#pragma unroll
            for (int nt = 0; nt < 8; ++nt)
#pragma unroll
                for (int cc = 0; cc < 2; ++cc) {
                    float v = as[nt][hf*2 + cc];
                    float p = (v > -1e29f) ? __expf(v - mn) : 0.f;
                    as[nt][hf*2 + cc] = p;
                    sl += p;
                }
            sl += __shfl_xor_sync(0xffffffffu, sl, 1);
            sl += __shfl_xor_sync(0xffffffffu, sl, 2);
            l_i[hf] = l_i[hf] * scale_[hf] + sl;
        }
#pragma unroll
        for (int nt = 0; nt < 16; ++nt) {
            ao[nt][0] *= scale_[0]; ao[nt][1] *= scale_[0];
            ao[nt][2] *= scale_[1]; ao[nt][3] *= scale_[1];
        }

        // ---- stage next KV into the idle buffer (overlap with PV below) ----
        if (st < stL) stKV(bsel ^ 1);
        if (st + 2 <= stL) ldKV(st + 2);

        // ---- O += P V (P split in regs; x4 trans V loads) ----
#pragma unroll
        for (int kc = 0; kc < 4; ++kc) {
            uint32_t ph[4], pl[4];
#pragma unroll
            for (int half = 0; half < 2; ++half) {
                const int nt = 2*kc + half;
                float p0 = as[nt][0], p1 = as[nt][1], p2 = as[nt][2], p3 = as[nt][3];
                float h0 = __bfloat162float(__float2bfloat16(p0));
                float h1 = __bfloat162float(__float2bfloat16(p1));
                float h2 = __bfloat162float(__float2bfloat16(p2));
                float h3 = __bfloat162float(__float2bfloat16(p3));
                ph[half*2 + 0] = pack_bf2(p0, p1);
                ph[half*2 + 1] = pack_bf2(p2, p3);
                pl[half*2 + 0] = pack_bf2(p0 - h0, p1 - h1);
                pl[half*2 + 1] = pack_bf2(p2 - h2, p3 - h3);
            }
#pragma unroll
            for (int ntp = 0; ntp < 8; ++ntp) {
                uint32_t va = vhB + (kc*16 + (lane & 15)) * AROW
                            + ntp*32 + (lane >> 4) * 16;
                uint32_t vh4[4], vl4[4];
                LDSM4T(vh4, va);
                LDSM4T(vl4, va + KTILE);
#pragma unroll
                for (int j = 0; j < 2; ++j) {
                    const int nt = ntp*2 + j;
                    MMA16816(ao[nt], ph, &vh4[2*j]);
                    MMA16816(ao[nt], pl, &vh4[2*j]);
                    MMA16816(ao[nt], ph, &vl4[2*j]);
                }
            }
        }

        __syncthreads();
    }

    // ---- epilogue: normalize, store fp32 encoded ----
#pragma unroll
    for (int hf = 0; hf < 2; ++hf) {
        const int qrow = q0 + row0 + rg + hf*8;
        const float inv = 1.0f / l_i[hf];
        float* o = g_enc + ((size_t)(b*CT + qrow) * CN + n) * CH;
#pragma unroll
        for (int nt = 0; nt < 16; ++nt)
            *(float2*)(o + nt*8 + tg*2) =
                make_float2(ao[nt][hf*2 + 0] * inv, ao[nt][hf*2 + 1] * inv);
    }
}

// ---------------------------------------------------------------------------
extern "C" void kernel_launch(void* const* d_in, const int* in_sizes, int n_in,
                              void* d_out, int out_size)
{
    const float* x   = (const float*)d_in[0];
    const float* wq  = (const float*)d_in[1];
    const float* wkv = (const float*)d_in[2];
    const float* wo  = (const float*)d_in[3];
    const int*   seg = (const int*)d_in[4];
    float* out = (float*)d_out;

    cudaFuncSetAttribute(attn_kernel,
                         cudaFuncAttributeMaxDynamicSharedMemorySize, ATT_SMEM);
    cudaFuncSetAttribute(qkv_kernel,
                         cudaFuncAttributeMaxDynamicSharedMemorySize, GEM_SMEM);
    cudaFuncSetAttribute(oproj_kernel,
                         cudaFuncAttributeMaxDynamicSharedMemorySize, GEM_SMEM);

    rope_init_kernel<<<1, 64>>>();
    qkv_kernel<<<dim3(32, 32), 256, GEM_SMEM>>>(x, wq, wkv);
    rope_kernel<<<(ROPE_QC + ROPE_KC + 255)/256, 256>>>(seg);
    attn_kernel<<<dim3(CT/128, CN, CB), 256, ATT_SMEM>>>();
    oproj_kernel<<<dim3(32, 16), 256, GEM_SMEM>>>(wo, out);
}

// round 11
// speedup vs baseline: 1.0087x; 1.0087x over previous
#include <cuda_runtime.h>
#include <cuda_bf16.h>
#include <math.h>
#include <stdint.h>

// Problem constants
#define CB 2
#define CT 2048
#define CD 2048
#define CN 16
#define CK 8
#define CH 128
#define CWIN 1024
#define CBT (CB*CT)

#define ROPE_QC (CB*CT*CN*64)
#define ROPE_KC (CB*CT*CK*64)

// Scratch (device globals; the exact 100.7MB set proven to pass the guard)
__device__ float g_q  [CBT*CN*CH];   // [B,T,N,H]
__device__ float g_k  [CBT*CK*CH];
__device__ float g_v  [CBT*CK*CH];
__device__ float g_enc[CBT*CN*CH];
__device__ float g_ts [64];

// ---------------------------------------------------------------------------
__global__ void rope_init_kernel() {
    int i = threadIdx.x;
    if (i < 64) g_ts[i] = (float)pow(10000.0, (double)i / 64.0);
}

__device__ __forceinline__ uint32_t pack_bf2(float x, float y) {
    __nv_bfloat162 h = __floats2bfloat162_rn(x, y);
    return *(uint32_t*)&h;
}

#define LDSM4(r, addr) \
    asm volatile("ldmatrix.sync.aligned.m8n8.x4.shared.b16 {%0,%1,%2,%3}, [%4];\n" \
        : "=r"((r)[0]), "=r"((r)[1]), "=r"((r)[2]), "=r"((r)[3]) : "r"(addr))
#define LDSM2T(r, addr) \
    asm volatile("ldmatrix.sync.aligned.m8n8.x2.trans.shared.b16 {%0,%1}, [%2];\n" \
        : "=r"((r)[0]), "=r"((r)[1]) : "r"(addr))
#define LDSM4T(r, addr) \
    asm volatile("ldmatrix.sync.aligned.m8n8.x4.trans.shared.b16 {%0,%1,%2,%3}, [%4];\n" \
        : "=r"((r)[0]), "=r"((r)[1]), "=r"((r)[2]), "=r"((r)[3]) : "r"(addr))
#define MMA16816(d, a, b) \
    asm volatile("mma.sync.aligned.m16n8k16.row.col.f32.bf16.bf16.f32 " \
        "{%0,%1,%2,%3}, {%4,%5,%6,%7}, {%8,%9}, {%0,%1,%2,%3};\n" \
        : "+f"((d)[0]), "+f"((d)[1]), "+f"((d)[2]), "+f"((d)[3]) \
        : "r"((a)[0]), "r"((a)[1]), "r"((a)[2]), "r"((a)[3]), "r"((b)[0]), "r"((b)[1]))

// ---------------------------------------------------------------------------
// Split-bf16 tensor-core GEMM (EXACT R4 structure; 2 CTAs/SM via launch bounds)
// ---------------------------------------------------------------------------
#define A_STR 40
#define B_STR 136
#define A_TILE (128*A_STR)
#define B_TILE (32*B_STR)
#define GEM_SMEM ((4*A_TILE + 4*B_TILE) * 2)

__device__ __forceinline__ void gemm_split_128x128(
    const float* __restrict__ A, int lda,
    const float* __restrict__ B, int ldb,
    float* __restrict__ C, int ldc, int Kd)
{
    extern __shared__ __nv_bfloat16 smg[];
    __nv_bfloat16* const sA = smg;
    __nv_bfloat16* const sB = smg + 4 * A_TILE;
    const uint32_t sAb = (uint32_t)__cvta_generic_to_shared(sA);
    const uint32_t sBb = (uint32_t)__cvta_generic_to_shared(sB);

    const int tid  = threadIdx.x;
    const int lane = tid & 31;
    const int wid  = tid >> 5;
    const int wm   = wid >> 2;
    const int wn   = wid & 3;

    const int ar = tid >> 1, ac = (tid & 1) * 4;
    const int br = tid >> 3, bc = (tid & 7) * 4;

    const float* Ap = A + (size_t)ar * lda + ac;
    const float* Bp = B + (size_t)br * ldb + bc;

    float acc[4][4][4];
#pragma unroll
    for (int a = 0; a < 4; ++a)
#pragma unroll
        for (int b = 0; b < 4; ++b)
#pragma unroll
            for (int c = 0; c < 4; ++c) acc[a][b][c] = 0.f;

    float4 av[4], bv[4];
#pragma unroll
    for (int q = 0; q < 4; ++q) {
        av[q] = *(const float4*)(Ap + q * 8);
        bv[q] = *(const float4*)(Bp + q * 32);
    }

    const int nIter = Kd >> 5;
    for (int it = 0; it < nIter; ++it) {
        const int cur = it & 1;
        __nv_bfloat16* aHi = sA + (2 * cur)     * A_TILE;
        __nv_bfloat16* aLo = sA + (2 * cur + 1) * A_TILE;
        __nv_bfloat16* bHi = sB + (2 * cur)     * B_TILE;
        __nv_bfloat16* bLo = sB + (2 * cur + 1) * B_TILE;

#pragma unroll
        for (int q = 0; q < 4; ++q) {
            float a0 = av[q].x, a1 = av[q].y, a2 = av[q].z, a3 = av[q].w;
            float h0 = __bfloat162float(__float2bfloat16(a0));
            float h1 = __bfloat162float(__float2bfloat16(a1));
            float h2 = __bfloat162float(__float2bfloat16(a2));
            float h3 = __bfloat162float(__float2bfloat16(a3));
            uint2 H = make_uint2(pack_bf2(h0, h1), pack_bf2(h2, h3));
            uint2 L = make_uint2(pack_bf2(a0 - h0, a1 - h1), pack_bf2(a2 - h2, a3 - h3));
            *(uint2*)(aHi + ar * A_STR + ac + q * 8) = H;
            *(uint2*)(aLo + ar * A_STR + ac + q * 8) = L;

            float b0 = bv[q].x, b1 = bv[q].y, b2 = bv[q].z, b3 = bv[q].w;
            float g0 = __bfloat162float(__float2bfloat16(b0));
            float g1 = __bfloat162float(__float2bfloat16(b1));
            float g2 = __bfloat162float(__float2bfloat16(b2));
            float g3 = __bfloat162float(__float2bfloat16(b3));
            H = make_uint2(pack_bf2(g0, g1), pack_bf2(g2, g3));
            L = make_uint2(pack_bf2(b0 - g0, b1 - g1), pack_bf2(b2 - g2, b3 - g3));
            *(uint2*)(bHi + br * B_STR + bc + q * 32) = H;
            *(uint2*)(bLo + br * B_STR + bc + q * 32) = L;
        }
        __syncthreads();

        if (it + 1 < nIter) {
            const float* An = Ap + (it + 1) * 32;
            const float* Bn = Bp + (size_t)(it + 1) * 32 * ldb;
#pragma unroll
            for (int q = 0; q < 4; ++q) {
                av[q] = *(const float4*)(An + q * 8);
                bv[q] = *(const float4*)(Bn + q * 32);
            }
        }

        const uint32_t aHiB = sAb + (2 * cur)     * A_TILE * 2;
        const uint32_t aLoB = sAb + (2 * cur + 1) * A_TILE * 2;
        const uint32_t bHiB = sBb + (2 * cur)     * B_TILE * 2;
        const uint32_t bLoB = sBb + (2 * cur + 1) * B_TILE * 2;

#pragma unroll
        for (int ks = 0; ks < 32; ks += 16) {
            uint32_t bhi[4][2], blo[4][2];
#pragma unroll
            for (int nt = 0; nt < 4; ++nt) {
                uint32_t off = (ks + (lane & 15)) * (B_STR * 2) + (wn * 32 + nt * 8) * 2;
                LDSM2T(bhi[nt], bHiB + off);
                LDSM2T(blo[nt], bLoB + off);
            }
#pragma unroll
            for (int mt = 0; mt < 4; ++mt) {
                int row = wm * 64 + mt * 16 + (lane & 15);
                uint32_t off = row * (A_STR * 2) + ks * 2 + (lane >> 4) * 16;
                uint32_t ahi[4], alo[4];
                LDSM4(ahi, aHiB + off);
                LDSM4(alo, aLoB + off);
#pragma unroll
                for (int nt = 0; nt < 4; ++nt) {
                    MMA16816(acc[mt][nt], ahi, bhi[nt]);
                    MMA16816(acc[mt][nt], alo, bhi[nt]);
                    MMA16816(acc[mt][nt], ahi, blo[nt]);
                }
            }
        }
    }

    const int rg = lane >> 2, tg = lane & 3;
#pragma unroll
    for (int mt = 0; mt < 4; ++mt)
#pragma unroll
        for (int nt = 0; nt < 4; ++nt) {
            int r = wm * 64 + mt * 16 + rg;
            int c = wn * 32 + nt * 8 + tg * 2;
            *(float2*)&C[(size_t)r * ldc + c]       = make_float2(acc[mt][nt][0], acc[mt][nt][1]);
            *(float2*)&C[(size_t)(r + 8) * ldc + c] = make_float2(acc[mt][nt][2], acc[mt][nt][3]);
        }
}

// ---------------------------------------------------------------------------
__global__ __launch_bounds__(256, 2) void qkv_kernel(
    const float* __restrict__ x,
    const float* __restrict__ wq,
    const float* __restrict__ wkv)
{
    const int m0 = blockIdx.x * 128;
    const int h  = blockIdx.y;
    const float* A = x + (size_t)m0 * CD;
    const float* W;
    float* C; int ldc;
    if (h < CN) {
        W = wq + (size_t)h * CD * CH;
        C = g_q + (size_t)m0 * CN * CH + h * CH; ldc = CN * CH;
    } else if (h < CN + CK) {
        const int kk = h - CN;
        W = wkv + (size_t)kk * CD * CH;
        C = g_k + (size_t)m0 * CK * CH + kk * CH; ldc = CK * CH;
    } else {
        const int kk = h - CN - CK;
        W = wkv + (size_t)(CK + kk) * CD * CH;
        C = g_v + (size_t)m0 * CK * CH + kk * CH; ldc = CK * CH;
    }
    gemm_split_128x128(A, CD, W, CH, C, ldc, CD);
}

__global__ __launch_bounds__(256, 2) void oproj_kernel(
    const float* __restrict__ wo, float* __restrict__ out)
{
    const int m0 = blockIdx.x * 128;
    const int n0 = blockIdx.y * 128;
    gemm_split_128x128(g_enc + (size_t)m0 * (CN*CH), CN*CH,
                       wo + n0, CD,
                       out + (size_t)m0 * CD + n0, CD, CN*CH);
}

// ---------------------------------------------------------------------------
__global__ __launch_bounds__(256) void rope_kernel(const int* __restrict__ seg)
{
    int idx = blockIdx.x * blockDim.x + threadIdx.x;
    if (idx >= ROPE_QC + ROPE_KC) return;

    float* buf; int heads; float scal; int lidx;
    if (idx < ROPE_QC) {
        buf = g_q; heads = CN; scal = 0.08838834764831845f; lidx = idx;
    } else {
        buf = g_k; heads = CK; scal = 1.0f; lidx = idx - ROPE_QC;
    }
    const int i    = lidx & 63;
    const int rest = lidx >> 6;
    const int bt   = rest / heads;
    const int pos  = seg[bt];

    float ts = g_ts[i];
    float ang = (float)pos / ts;
    float s, c;
    sincosf(ang, &s, &c);

    float* p = buf + (size_t)rest * CH;
    float x1 = p[i];
    float x2 = p[i + 64];
    p[i]      = (x1 * c - x2 * s) * scal;
    p[i + 64] = (x2 * c + x1 * s) * scal;
}

// ---------------------------------------------------------------------------
__device__ __forceinline__ float softcap(float v)
{
    float x = v * (1.0f / 50.0f);
    float ax = fabsf(x);
    if (ax < 0.25f) {
        float x2 = x * x;
        float t = x * (1.0f + x2 * (-1.0f/3.0f + x2 * (2.0f/15.0f + x2 * (-17.0f/315.0f))));
        return t * 50.0f;
    }
    return tanhf(x) * 50.0f;
}

// ---------------------------------------------------------------------------
// Tensor-core flash attention (R9 version; measured equal to R8)
// ---------------------------------------------------------------------------
#define AROW 272
#define QTILE (128*AROW)
#define KTILE (64*AROW)
#define ASTG  (4*KTILE)
#define AKV0  (2*QTILE)
#define ATT_SMEM (AKV0 + 2*ASTG)

__global__ __launch_bounds__(256, 1) void attn_kernel()
{
    extern __shared__ char sma[];
    const uint32_t sb = (uint32_t)__cvta_generic_to_shared(sma);

    const int tid = threadIdx.x, lane = tid & 31, w = tid >> 5;
    const int rg = lane >> 2, tg = lane & 3;
    const int qt = blockIdx.x, n = blockIdx.y, b = blockIdx.z;
    const int kk = n >> 1;
    const int q0 = qt * 128;
    const int row0 = w * 16;

#pragma unroll
    for (int p = 0; p < 16; ++p) {
        int idx = tid + p * 256;
        int r = idx >> 5, c4 = idx & 31;
        float4 f = *(const float4*)(g_q +
            ((size_t)(b*CT + q0 + r) * CN + n) * CH + c4 * 4);
        float h0 = __bfloat162float(__float2bfloat16(f.x));
        float h1 = __bfloat162float(__float2bfloat16(f.y));
        float h2 = __bfloat162float(__float2bfloat16(f.z));
        float h3 = __bfloat162float(__float2bfloat16(f.w));
        uint32_t off = (uint32_t)(r * AROW + c4 * 8);
        *(uint2*)(sma + off)         = make_uint2(pack_bf2(h0, h1), pack_bf2(h2, h3));
        *(uint2*)(sma + QTILE + off) = make_uint2(pack_bf2(f.x - h0, f.y - h1),
                                                  pack_bf2(f.z - h2, f.w - h3));
    }

    int st0 = q0 - (CWIN - 1); if (st0 < 0) st0 = 0; st0 >>= 6;
    const int stL = (q0 + 127) >> 6;

    float4 kreg[8], vreg[8];
    const int sr = tid >> 5, sc = tid & 31;

    auto ldKV = [&](int st) {
        const int s0 = st * 64;
#pragma unroll
        for (int p = 0; p < 8; ++p) {
            int r = sr + p * 8;
            size_t off = ((size_t)(b*CT + s0 + r) * CK + kk) * CH + sc * 4;
            kreg[p] = *(const float4*)(g_k + off);
            vreg[p] = *(const float4*)(g_v + off);
        }
    };
    auto stKV = [&](int bsel) {
        const uint32_t kb = AKV0 + bsel * ASTG;
#pragma unroll
        for (int p = 0; p < 8; ++p) {
            int r = sr + p * 8;
            uint32_t off = (uint32_t)(r * AROW + sc * 8);
            float4 f = kreg[p];
            float h0 = __bfloat162float(__float2bfloat16(f.x));
            float h1 = __bfloat162float(__float2bfloat16(f.y));
            float h2 = __bfloat162float(__float2bfloat16(f.z));
            float h3 = __bfloat162float(__float2bfloat16(f.w));
            *(uint2*)(sma + kb + off) = make_uint2(pack_bf2(h0, h1), pack_bf2(h2, h3));
            *(uint2*)(sma + kb + KTILE + off) =
                make_uint2(pack_bf2(f.x - h0, f.y - h1), pack_bf2(f.z - h2, f.w - h3));
            f = vreg[p];
            h0 = __bfloat162float(__float2bfloat16(f.x));
            h1 = __bfloat162float(__float2bfloat16(f.y));
            h2 = __bfloat162float(__float2bfloat16(f.z));
            h3 = __bfloat162float(__float2bfloat16(f.w));
            *(uint2*)(sma + kb + 2*KTILE + off) = make_uint2(pack_bf2(h0, h1), pack_bf2(h2, h3));
            *(uint2*)(sma + kb + 3*KTILE + off) =
                make_uint2(pack_bf2(f.x - h0, f.y - h1), pack_bf2(f.z - h2, f.w - h3));
        }
    };

    ldKV(st0);
    stKV(0);
    if (st0 + 1 <= stL) ldKV(st0 + 1);
    __syncthreads();

    float m_i[2] = {-1e30f, -1e30f}, l_i[2] = {0.f, 0.f};
    float ao[16][4];
#pragma unroll
    for (int t = 0; t < 16; ++t)
#pragma unroll
        for (int c = 0; c < 4; ++c) ao[t][c] = 0.f;

    for (int st = st0; st <= stL; ++st) {
        const int bsel = (st - st0) & 1;
        const uint32_t kb  = sb + AKV0 + bsel * ASTG;
        const uint32_t vhB = kb + 2*KTILE;
        const int s0 = st * 64;

        float as[8][4];
#pragma unroll
        for (int nt = 0; nt < 8; ++nt)
#pragma unroll
            for (int c = 0; c < 4; ++c) as[nt][c] = 0.f;

#pragma unroll
        for (int kc = 0; kc < 8; ++kc) {
            uint32_t qa = sb + (row0 + (lane & 15)) * AROW + kc*32 + (lane >> 4) * 16;
            uint32_t qh[4], ql[4];
            LDSM4(qh, qa);
            LDSM4(ql, qa + QTILE);
#pragma unroll
            for (int ntp = 0; ntp < 4; ++ntp) {
                uint32_t ka = kb + (ntp*16 + (lane >> 4)*8 + (lane & 7)) * AROW
                            + kc*32 + ((lane >> 3) & 1) * 16;
                uint32_t kh4[4], kl4[4];
                LDSM4(kh4, ka);
                LDSM4(kl4, ka + KTILE);
#pragma unroll
                for (int j = 0; j < 2; ++j) {
                    const int nt = ntp*2 + j;
                    MMA16816(as[nt], qh, &kh4[2*j]);
                    MMA16816(as[nt], ql, &kh4[2*j]);
                    MMA16816(as[nt], qh, &kl4[2*j]);
                }
            }
        }

        float scale_[2];
#pragma unroll
        for (int hf = 0; hf < 2; ++hf) {
            const int qrow = q0 + row0 + rg + hf*8;
            float rm = -1e30f;
#pragma unroll
            for (int nt = 0; nt < 8; ++nt)
#pragma unroll
                for (int cc = 0; cc < 2; ++cc) {
                    const int scol = s0 + nt*8 + tg*2 + cc;
                    float xx = softcap(as[nt][hf*2 + cc]);
                    const bool valid = (scol <= qrow) && (qrow - scol < CWIN);
                    xx = valid ? xx : -1e30f;
                    as[nt][hf*2 + cc] = xx;
                    rm = fmaxf(rm, xx);
                }
            rm = fmaxf(rm, __shfl_xor_sync(0xffffffffu, rm, 1));
            rm = fmaxf(rm, __shfl_xor_sync(0xffffffffu, rm, 2));

            const float mn = fmaxf(m_i[hf], rm);
            scale_[hf] = __expf(m_i[hf] - mn);
            m_i[hf] = mn;

            float sl = 0.f;
#pragma unroll
            for (int nt = 0; nt < 8; ++nt)
#pragma unroll
                for (int cc = 0; cc < 2; ++cc) {
                    float v = as[nt][hf*2 + cc];
                    float p = (v > -1e29f) ? __expf(v - mn) : 0.f;
                    as[nt][hf*2 + cc] = p;
                    sl += p;
                }
            sl += __shfl_xor_sync(0xffffffffu, sl, 1);
            sl += __shfl_xor_sync(0xffffffffu, sl, 2);
            l_i[hf] = l_i[hf] * scale_[hf] + sl;
        }
#pragma unroll
        for (int nt = 0; nt < 16; ++nt) {
            ao[nt][0] *= scale_[0]; ao[nt][1] *= scale_[0];
            ao[nt][2] *= scale_[1]; ao[nt][3] *= scale_[1];
        }

        if (st < stL) stKV(bsel ^ 1);
        if (st + 2 <= stL) ldKV(st + 2);

#pragma unroll
        for (int kc = 0; kc < 4; ++kc) {
            uint32_t ph[4], pl[4];
#pragma unroll
            for (int half = 0; half < 2; ++half) {
                const int nt = 2*kc + half;
                float p0 = as[nt][0], p1 = as[nt][1], p2 = as[nt][2], p3 = as[nt][3];
                float h0 = __bfloat162float(__float2bfloat16(p0));
                float h1 = __bfloat162float(__float2bfloat16(p1));
                float h2 = __bfloat162float(__float2bfloat16(p2));
                float h3 = __bfloat162float(__float2bfloat16(p3));
                ph[half*2 + 0] = pack_bf2(p0, p1);
                ph[half*2 + 1] = pack_bf2(p2, p3);
                pl[half*2 + 0] = pack_bf2(p0 - h0, p1 - h1);
                pl[half*2 + 1] = pack_bf2(p2 - h2, p3 - h3);
            }
#pragma unroll
            for (int ntp = 0; ntp < 8; ++ntp) {
                uint32_t va = vhB + (kc*16 + (lane & 15)) * AROW
                            + ntp*32 + (lane >> 4) * 16;
                uint32_t vh4[4], vl4[4];
                LDSM4T(vh4, va);
                LDSM4T(vl4, va + KTILE);
#pragma unroll
                for (int j = 0; j < 2; ++j) {
                    const int nt = ntp*2 + j;
                    MMA16816(ao[nt], ph, &vh4[2*j]);
                    MMA16816(ao[nt], pl, &vh4[2*j]);
                    MMA16816(ao[nt], ph, &vl4[2*j]);
                }
            }
        }

        __syncthreads();
    }

#pragma unroll
    for (int hf = 0; hf < 2; ++hf) {
        const int qrow = q0 + row0 + rg + hf*8;
        const float inv = 1.0f / l_i[hf];
        float* o = g_enc + ((size_t)(b*CT + qrow) * CN + n) * CH;
#pragma unroll
        for (int nt = 0; nt < 16; ++nt)
            *(float2*)(o + nt*8 + tg*2) =
                make_float2(ao[nt][hf*2 + 0] * inv, ao[nt][hf*2 + 1] * inv);
    }
}

// ---------------------------------------------------------------------------
extern "C" void kernel_launch(void* const* d_in, const int* in_sizes, int n_in,
                              void* d_out, int out_size)
{
    const float* x   = (const float*)d_in[0];
    const float* wq  = (const float*)d_in[1];
    const float* wkv = (const float*)d_in[2];
    const float* wo  = (const float*)d_in[3];
    const int*   seg = (const int*)d_in[4];
    float* out = (float*)d_out;

    cudaFuncSetAttribute(attn_kernel,
                         cudaFuncAttributeMaxDynamicSharedMemorySize, ATT_SMEM);
    cudaFuncSetAttribute(qkv_kernel,
                         cudaFuncAttributeMaxDynamicSharedMemorySize, GEM_SMEM);
    cudaFuncSetAttribute(oproj_kernel,
                         cudaFuncAttributeMaxDynamicSharedMemorySize, GEM_SMEM);

    rope_init_kernel<<<1, 64>>>();
    qkv_kernel<<<dim3(32, 32), 256, GEM_SMEM>>>(x, wq, wkv);
    rope_kernel<<<(ROPE_QC + ROPE_KC + 255)/256, 256>>>(seg);
    attn_kernel<<<dim3(CT/128, CN, CB), 256, ATT_SMEM>>>();
    oproj_kernel<<<dim3(32, 16), 256, GEM_SMEM>>>(wo, out);
}